// round 1
// baseline (speedup 1.0000x reference)
#include <cuda_runtime.h>
#include <math.h>

#define NN 100000
#define EE 1600000
#define CC 128

// Scratch buffers (allocation-free rule: __device__ globals)
__device__ float g_h[(size_t)NN * CC];
__device__ float g_nb[(size_t)NN * CC];
__device__ float g_self[(size_t)NN * CC];
__device__ float g_aggr[(size_t)NN * CC];
__device__ float g_u[(size_t)NN * CC];

__device__ __forceinline__ float gelu_f(float v) {
    // exact gelu: 0.5*v*(1+erf(v/sqrt(2)))
    return 0.5f * v * (1.0f + erff(v * 0.7071067811865475f));
}

// ---------------------------------------------------------------------------
// Lift stage 1: hid = gelu(nf @ W1 + b1), nf = x[:, 3:9]  (6 -> 128)
// ---------------------------------------------------------------------------
__global__ void lift_hidden_kernel(const float* __restrict__ x,
                                   const float* __restrict__ w1,
                                   const float* __restrict__ b1) {
    int idx = blockIdx.x * blockDim.x + threadIdx.x;
    if (idx >= NN * CC) return;
    int n = idx >> 7;
    int c = idx & 127;
    const float* xr = x + (size_t)n * 9 + 3;
    float acc = b1[c];
#pragma unroll
    for (int i = 0; i < 6; i++)
        acc = fmaf(xr[i], w1[i * CC + c], acc);
    g_u[idx] = gelu_f(acc);
}

// ---------------------------------------------------------------------------
// Generic fp32 GEMM: Out[M x 128] = act(A @ W + bias) (+ residual)
//   A is [M x K] row-major, supplied as A0 (k<128) and A1 (k>=128, for K=256).
//   W is [K x 128] row-major.
// Tile: BM=128, BN=128, BK=16; 256 threads; 8x8 register tile per thread.
// ---------------------------------------------------------------------------
template <int GELU, int RESID>
__global__ void gemm_kernel(const float* __restrict__ A0,
                            const float* __restrict__ A1,
                            const float* __restrict__ W,
                            const float* __restrict__ bias,
                            const float* __restrict__ R,
                            float* __restrict__ Out,
                            int K) {
    __shared__ __align__(16) float As[16][132];
    __shared__ __align__(16) float Ws[16][132];

    const int tid = threadIdx.x;
    const int tx = tid & 15;   // column group: cols tx*8 .. tx*8+7
    const int ty = tid >> 4;   // row group:    rows ty*8 .. ty*8+7
    const int m0 = blockIdx.x * 128;

    float acc[8][8];
#pragma unroll
    for (int i = 0; i < 8; i++)
#pragma unroll
        for (int j = 0; j < 8; j++) acc[i][j] = 0.0f;

    for (int k0 = 0; k0 < K; k0 += 16) {
        const float* Asrc = (k0 < 128) ? A0 : A1;
        const int kk = k0 & 127;

        // Load A tile (128 rows x 16 k) -> transposed into As[k][m]
#pragma unroll
        for (int i = 0; i < 2; i++) {
            int s = tid + i * 256;        // float4 slot 0..511
            int m = s >> 2;               // 0..127
            int kq = (s & 3) * 4;         // 0,4,8,12
            int gm = m0 + m;
            float4 v = make_float4(0.f, 0.f, 0.f, 0.f);
            if (gm < NN)
                v = *(const float4*)(Asrc + (size_t)gm * 128 + kk + kq);
            As[kq + 0][m] = v.x;
            As[kq + 1][m] = v.y;
            As[kq + 2][m] = v.z;
            As[kq + 3][m] = v.w;
        }
        // Load W tile (16 k x 128 cols)
#pragma unroll
        for (int i = 0; i < 2; i++) {
            int s = tid + i * 256;        // float4 slot 0..511
            int kw = s >> 5;              // 0..15
            int c = (s & 31) * 4;         // 0..124
            float4 v = *(const float4*)(W + (size_t)(k0 + kw) * 128 + c);
            *(float4*)&Ws[kw][c] = v;
        }
        __syncthreads();

#pragma unroll
        for (int k = 0; k < 16; k++) {
            float a[8], wv[8];
            *(float4*)(a)      = *(const float4*)&As[k][ty * 8];
            *(float4*)(a + 4)  = *(const float4*)&As[k][ty * 8 + 4];
            *(float4*)(wv)     = *(const float4*)&Ws[k][tx * 8];
            *(float4*)(wv + 4) = *(const float4*)&Ws[k][tx * 8 + 4];
#pragma unroll
            for (int i = 0; i < 8; i++)
#pragma unroll
                for (int j = 0; j < 8; j++)
                    acc[i][j] = fmaf(a[i], wv[j], acc[i][j]);
        }
        __syncthreads();
    }

    // Epilogue
    float bj[8];
#pragma unroll
    for (int j = 0; j < 8; j++) bj[j] = bias[tx * 8 + j];

#pragma unroll
    for (int i = 0; i < 8; i++) {
        int gm = m0 + ty * 8 + i;
        if (gm >= NN) continue;
        float* orow = Out + (size_t)gm * 128 + tx * 8;
        float res[8];
        if (RESID) {
            const float* rrow = R + (size_t)gm * 128 + tx * 8;
            *(float4*)(res)     = *(const float4*)(rrow);
            *(float4*)(res + 4) = *(const float4*)(rrow + 4);
        }
        float o[8];
#pragma unroll
        for (int j = 0; j < 8; j++) {
            float v = acc[i][j] + bj[j];
            if (GELU) v = gelu_f(v);
            if (RESID) v += res[j];
            o[j] = v;
        }
        *(float4*)(orow)     = *(const float4*)(o);
        *(float4*)(orow + 4) = *(const float4*)(o + 4);
    }
}

// ---------------------------------------------------------------------------
// Zero the aggregation buffer
// ---------------------------------------------------------------------------
__global__ void zero_aggr_kernel() {
    int idx = blockIdx.x * blockDim.x + threadIdx.x;
    if (idx < NN * CC / 4)
        ((float4*)g_aggr)[idx] = make_float4(0.f, 0.f, 0.f, 0.f);
}

// ---------------------------------------------------------------------------
// Edge kernel: aggr[row] += neighbor[col] * ev.  One warp per edge.
// Loads and atomics are consecutive-address per instruction -> fully coalesced
// 128B transactions / sector RMWs.
// ---------------------------------------------------------------------------
__global__ void edge_kernel(const int* __restrict__ ei,
                            const float* __restrict__ ev) {
    int e = blockIdx.x * 8 + (threadIdx.x >> 5);
    if (e >= EE) return;
    int lane = threadIdx.x & 31;
    int row = ei[e];
    int col = ei[EE + e];
    float v = ev[e];
    const float* s = g_nb + (size_t)col * CC + lane;
    float* d = g_aggr + (size_t)row * CC + lane;
#pragma unroll
    for (int i = 0; i < 4; i++)
        atomicAdd(d + i * 32, s[i * 32] * v);
}

// ---------------------------------------------------------------------------
// LayerNorm over C=128, one warp per node, writes final output.
// ---------------------------------------------------------------------------
__global__ void ln_kernel(const float* __restrict__ h,
                          const float* __restrict__ g,
                          const float* __restrict__ b,
                          float* __restrict__ out) {
    int n = blockIdx.x * 8 + (threadIdx.x >> 5);
    if (n >= NN) return;
    int lane = threadIdx.x & 31;
    const float* r = h + (size_t)n * CC;
    float v[4];
    float s = 0.f;
#pragma unroll
    for (int i = 0; i < 4; i++) {
        v[i] = r[lane + i * 32];
        s += v[i];
    }
#pragma unroll
    for (int o = 16; o; o >>= 1) s += __shfl_xor_sync(0xffffffffu, s, o);
    float mu = s * (1.f / 128.f);
    float q = 0.f;
#pragma unroll
    for (int i = 0; i < 4; i++) {
        float d = v[i] - mu;
        q = fmaf(d, d, q);
    }
#pragma unroll
    for (int o = 16; o; o >>= 1) q += __shfl_xor_sync(0xffffffffu, q, o);
    float inv = rsqrtf(q * (1.f / 128.f) + 1e-5f);
#pragma unroll
    for (int i = 0; i < 4; i++) {
        int c = lane + i * 32;
        out[(size_t)n * CC + c] = fmaf((v[i] - mu) * inv, g[c], b[c]);
    }
}

// ---------------------------------------------------------------------------
extern "C" void kernel_launch(void* const* d_in, const int* in_sizes, int n_in,
                              void* d_out, int out_size) {
    const float* x   = (const float*)d_in[0];
    const int*   ei  = (const int*)d_in[1];
    const float* ev  = (const float*)d_in[2];
    const float* lw1 = (const float*)d_in[3];
    const float* lb1 = (const float*)d_in[4];
    const float* lw2 = (const float*)d_in[5];
    const float* lb2 = (const float*)d_in[6];
    const float* sw  = (const float*)d_in[7];
    const float* sb  = (const float*)d_in[8];
    const float* nw  = (const float*)d_in[9];
    const float* nbw = (const float*)d_in[10];
    const float* gw1 = (const float*)d_in[11];
    const float* gb1 = (const float*)d_in[12];
    const float* gw2 = (const float*)d_in[13];
    const float* gb2 = (const float*)d_in[14];
    const float* ng  = (const float*)d_in[15];
    const float* nbt = (const float*)d_in[16];
    float* out = (float*)d_out;

    float *h, *nbuf, *selfb, *aggr, *u;
    cudaGetSymbolAddress((void**)&h, g_h);
    cudaGetSymbolAddress((void**)&nbuf, g_nb);
    cudaGetSymbolAddress((void**)&selfb, g_self);
    cudaGetSymbolAddress((void**)&aggr, g_aggr);
    cudaGetSymbolAddress((void**)&u, g_u);

    const int GB = (NN + 127) / 128;  // 782 blocks per GEMM

    // Lift: hid = gelu(nf @ W1 + b1); h = hid @ W2 + b2
    lift_hidden_kernel<<<(NN * CC + 255) / 256, 256>>>(x, lw1, lb1);
    gemm_kernel<0, 0><<<GB, 256>>>(u, nullptr, lw2, lb2, nullptr, h, 128);

    for (int l = 0; l < 2; l++) {
        // neighbor = h @ Wn + bn
        gemm_kernel<0, 0><<<GB, 256>>>(h, nullptr, nw + (size_t)l * CC * CC,
                                       nbw + l * CC, nullptr, nbuf, 128);
        // aggr = scatter_add(neighbor[col] * ev, row)
        zero_aggr_kernel<<<NN * CC / 4 / 256 + 1, 256>>>();
        edge_kernel<<<EE / 8, 256>>>(ei, ev);
        // self_f = h @ Ws + bs
        gemm_kernel<0, 0><<<GB, 256>>>(h, nullptr, sw + (size_t)l * CC * CC,
                                       sb + l * CC, nullptr, selfb, 128);
        // u = gelu([self_f, aggr] @ Wg1 + bg1)
        gemm_kernel<1, 0><<<GB, 256>>>(selfb, aggr, gw1 + (size_t)l * 2 * CC * CC,
                                       gb1 + l * CC, nullptr, u, 256);
        // h = h + u @ Wg2 + bg2
        gemm_kernel<0, 1><<<GB, 256>>>(u, nullptr, gw2 + (size_t)l * CC * CC,
                                       gb2 + l * CC, h, h, 128);
    }

    ln_kernel<<<(NN + 7) / 8, 256>>>(h, ng, nbt, out);
}

// round 3
// speedup vs baseline: 1.3611x; 1.3611x over previous
#include <cuda_runtime.h>
#include <cuda_bf16.h>
#include <math.h>
#include <stdint.h>

#define NN 100000
#define EE 1600000
#define CC 128

// ---------------------------------------------------------------------------
// Scratch (allocation-free rule: __device__ globals)
// ---------------------------------------------------------------------------
__device__ float g_h[(size_t)NN * CC];
__device__ float g_nb[(size_t)NN * CC];
__device__ float g_self[(size_t)NN * CC];
__device__ float g_aggr[(size_t)NN * CC];
__device__ float g_u[(size_t)NN * CC];

// Pre-converted bf16 weight tiles (hi/lo split), layout [slot][n][k] (k contig)
// = col-major B for mma .row.col. Slots: [0]=lift2; per layer l:
// [1+5l]=neigh, [2+5l]=self, [3+5l]=gate1 k<128, [4+5l]=gate1 k>=128, [5+5l]=gate2.
#define WSLOTS 11
__device__ __nv_bfloat16 g_wbh[(size_t)WSLOTS * 16384];
__device__ __nv_bfloat16 g_wbl[(size_t)WSLOTS * 16384];

__device__ __forceinline__ float gelu_f(float v) {
    return 0.5f * v * (1.0f + erff(v * 0.7071067811865475f));
}

// ---------------------------------------------------------------------------
// mma.sync helpers (arch-generic PTX, HMMA on sm_103)
// ---------------------------------------------------------------------------
__device__ __forceinline__ void ldsm_x4(uint32_t* r, uint32_t addr) {
    asm volatile("ldmatrix.sync.aligned.m8n8.x4.shared.b16 {%0,%1,%2,%3}, [%4];"
                 : "=r"(r[0]), "=r"(r[1]), "=r"(r[2]), "=r"(r[3]) : "r"(addr));
}
__device__ __forceinline__ void mma16816(float* d, const uint32_t* a, const uint32_t* b) {
    asm volatile(
        "mma.sync.aligned.m16n8k16.row.col.f32.bf16.bf16.f32 "
        "{%0,%1,%2,%3}, {%4,%5,%6,%7}, {%8,%9}, {%0,%1,%2,%3};"
        : "+f"(d[0]), "+f"(d[1]), "+f"(d[2]), "+f"(d[3])
        : "r"(a[0]), "r"(a[1]), "r"(a[2]), "r"(a[3]), "r"(b[0]), "r"(b[1]));
}

// ---------------------------------------------------------------------------
// Weight conversion: fp32 W[K,N] -> bf16 hi/lo B[N,K]
// ---------------------------------------------------------------------------
__global__ void wconv_kernel(const float* __restrict__ lw2,
                             const float* __restrict__ sw,
                             const float* __restrict__ nw,
                             const float* __restrict__ gw1,
                             const float* __restrict__ gw2) {
    int idx = blockIdx.x * blockDim.x + threadIdx.x;
    if (idx >= WSLOTS * 16384) return;
    int slot = idx >> 14;
    int within = idx & 16383;
    int n = within >> 7;
    int k = within & 127;
    const float* src;
    if (slot == 0) {
        src = lw2 + k * 128 + n;
    } else {
        int l = (slot - 1) / 5, j = (slot - 1) % 5;
        if (j == 0)      src = nw  + (size_t)l * 16384 + k * 128 + n;
        else if (j == 1) src = sw  + (size_t)l * 16384 + k * 128 + n;
        else if (j == 2) src = gw1 + (size_t)l * 32768 + k * 128 + n;
        else if (j == 3) src = gw1 + (size_t)l * 32768 + 16384 + k * 128 + n;
        else             src = gw2 + (size_t)l * 16384 + k * 128 + n;
    }
    float v = *src;
    __nv_bfloat16 hi = __float2bfloat16(v);
    __nv_bfloat16 lo = __float2bfloat16(v - __bfloat162float(hi));
    g_wbh[idx] = hi;
    g_wbl[idx] = lo;
}

// ---------------------------------------------------------------------------
// HMMA GEMM: Out[M x 128] = act(A @ W + bias) (+ residual)
// 3-term bf16 split. 128x128 tile/CTA, 8 warps (4M x 2N), 32x64 per warp.
// Smem rows padded to 272B for conflict-free ldmatrix.
// ---------------------------------------------------------------------------
#define ROWB 272
#define SM_AH 0
#define SM_AL (128 * ROWB)
#define SM_BH (2 * 128 * ROWB)
#define SM_BL (3 * 128 * ROWB)
#define SM_TOTAL (4 * 128 * ROWB)   // 139264 bytes

template <int GELU, int RESID>
__global__ void __launch_bounds__(256, 1) gemm_mma(
    const float* __restrict__ A0, const float* __restrict__ A1,
    const __nv_bfloat16* __restrict__ Bh, const __nv_bfloat16* __restrict__ Bl,
    const float* __restrict__ bias, const float* __restrict__ R,
    float* __restrict__ Out, int kchunks) {
    extern __shared__ __align__(16) char smem[];
    const uint32_t sb = (uint32_t)__cvta_generic_to_shared(smem);
    const int tid = threadIdx.x;
    const int wid = tid >> 5;
    const int lane = tid & 31;
    const int warp_m = wid >> 1;       // 0..3 -> rows warp_m*32
    const int warp_n = wid & 1;        // 0..1 -> cols warp_n*64
    const int m0 = blockIdx.x * 128;

    float acc[2][8][4];
#pragma unroll
    for (int mi = 0; mi < 2; mi++)
#pragma unroll
        for (int nt = 0; nt < 8; nt++)
#pragma unroll
            for (int e = 0; e < 4; e++) acc[mi][nt][e] = 0.0f;

    // ldmatrix per-lane base offsets (within a tile), in bytes
    // A (m16k16 row-major): row = (lane&7) + ((lane>>3)&1)*8 ; kblk = (lane>>4)*8
    const uint32_t a_lane = (uint32_t)(((lane & 7) + ((lane >> 3) & 1) * 8) * ROWB +
                                       (lane >> 4) * 16);
    // B (k16n8 col-major from [n][k]): n = (lane&7) + ((lane>>4)&1)*8 ; kblk = ((lane>>3)&1)*8
    const uint32_t b_lane = (uint32_t)(((lane & 7) + ((lane >> 4) & 1) * 8) * ROWB +
                                       ((lane >> 3) & 1) * 16);

    for (int c = 0; c < kchunks; c++) {
        const float* A = (c == 0) ? A0 : A1;
        const uint4* bhp = (const uint4*)(Bh + (size_t)c * 16384);
        const uint4* blp = (const uint4*)(Bl + (size_t)c * 16384);

        if (c) __syncthreads();

        // Stage weights (2048 x 16B per tile)
#pragma unroll
        for (int i = 0; i < 8; i++) {
            int ci = tid + i * 256;
            int row = ci >> 4, ch = ci & 15;
            uint32_t off = (uint32_t)(row * ROWB + ch * 16);
            *(uint4*)(smem + SM_BH + off) = bhp[ci];
            *(uint4*)(smem + SM_BL + off) = blp[ci];
        }
        // Stage A: fp32 -> bf16 hi/lo
#pragma unroll
        for (int i = 0; i < 8; i++) {
            int ci = tid + i * 256;
            int row = ci >> 4, ch = ci & 15;
            int gm = m0 + row;
            float v[8];
            if (gm < NN) {
                float4 a = *(const float4*)(A + (size_t)gm * 128 + ch * 8);
                float4 b = *(const float4*)(A + (size_t)gm * 128 + ch * 8 + 4);
                v[0] = a.x; v[1] = a.y; v[2] = a.z; v[3] = a.w;
                v[4] = b.x; v[5] = b.y; v[6] = b.z; v[7] = b.w;
            } else {
#pragma unroll
                for (int e = 0; e < 8; e++) v[e] = 0.0f;
            }
            __align__(16) __nv_bfloat16 h8[8], l8[8];
#pragma unroll
            for (int e = 0; e < 8; e++) {
                h8[e] = __float2bfloat16(v[e]);
                l8[e] = __float2bfloat16(v[e] - __bfloat162float(h8[e]));
            }
            uint32_t off = (uint32_t)(row * ROWB + ch * 16);
            *(uint4*)(smem + SM_AH + off) = *(uint4*)h8;
            *(uint4*)(smem + SM_AL + off) = *(uint4*)l8;
        }
        __syncthreads();

        // 3 terms: (Ah,Bh), (Ah,Bl), (Al,Bh)
#pragma unroll
        for (int t = 0; t < 3; t++) {
            const uint32_t abase = sb + ((t < 2) ? SM_AH : SM_AL) +
                                   (uint32_t)(warp_m * 32 * ROWB) + a_lane;
            const uint32_t bbase = sb + ((t == 1) ? SM_BL : SM_BH) +
                                   (uint32_t)(warp_n * 64 * ROWB) + b_lane;
#pragma unroll
            for (int ks = 0; ks < 8; ks++) {
                uint32_t af[2][4];
                ldsm_x4(af[0], abase + ks * 32);
                ldsm_x4(af[1], abase + ks * 32 + 16 * ROWB);
                uint32_t bf[4][4];
#pragma unroll
                for (int np = 0; np < 4; np++)
                    ldsm_x4(bf[np], bbase + ks * 32 + np * 16 * ROWB);
#pragma unroll
                for (int mi = 0; mi < 2; mi++)
#pragma unroll
                    for (int nt = 0; nt < 8; nt++) {
                        uint32_t bb[2] = { bf[nt >> 1][(nt & 1) * 2],
                                           bf[nt >> 1][(nt & 1) * 2 + 1] };
                        mma16816(acc[mi][nt], af[mi], bb);
                    }
            }
        }
    }

    // Epilogue
#pragma unroll
    for (int mi = 0; mi < 2; mi++) {
        int r0 = m0 + warp_m * 32 + mi * 16 + (lane >> 2);
#pragma unroll
        for (int half = 0; half < 2; half++) {
            int r = r0 + half * 8;
            if (r >= NN) continue;
            float* orow = Out + (size_t)r * 128;
            const float* rrow = RESID ? (R + (size_t)r * 128) : nullptr;
#pragma unroll
            for (int nt = 0; nt < 8; nt++) {
                int col = warp_n * 64 + nt * 8 + (lane & 3) * 2;
                float x0 = acc[mi][nt][half * 2 + 0] + __ldg(bias + col);
                float x1 = acc[mi][nt][half * 2 + 1] + __ldg(bias + col + 1);
                if (GELU) { x0 = gelu_f(x0); x1 = gelu_f(x1); }
                if (RESID) {
                    float2 rr = *(const float2*)(rrow + col);
                    x0 += rr.x; x1 += rr.y;
                }
                *(float2*)(orow + col) = make_float2(x0, x1);
            }
        }
    }
}

// ---------------------------------------------------------------------------
// Lift stage 1: hid = gelu(nf @ W1 + b1), nf = x[:, 3:9]  (6 -> 128)
// ---------------------------------------------------------------------------
__global__ void lift_hidden_kernel(const float* __restrict__ x,
                                   const float* __restrict__ w1,
                                   const float* __restrict__ b1) {
    int idx = blockIdx.x * blockDim.x + threadIdx.x;
    if (idx >= NN * CC) return;
    int n = idx >> 7;
    int c = idx & 127;
    const float* xr = x + (size_t)n * 9 + 3;
    float acc = b1[c];
#pragma unroll
    for (int i = 0; i < 6; i++)
        acc = fmaf(xr[i], w1[i * CC + c], acc);
    g_u[idx] = gelu_f(acc);
}

__global__ void zero_aggr_kernel() {
    int idx = blockIdx.x * blockDim.x + threadIdx.x;
    if (idx < NN * CC / 4)
        ((float4*)g_aggr)[idx] = make_float4(0.f, 0.f, 0.f, 0.f);
}

__global__ void edge_kernel(const int* __restrict__ ei,
                            const float* __restrict__ ev) {
    int e = blockIdx.x * 8 + (threadIdx.x >> 5);
    if (e >= EE) return;
    int lane = threadIdx.x & 31;
    int row = ei[e];
    int col = ei[EE + e];
    float v = ev[e];
    const float* s = g_nb + (size_t)col * CC + lane;
    float* d = g_aggr + (size_t)row * CC + lane;
#pragma unroll
    for (int i = 0; i < 4; i++)
        atomicAdd(d + i * 32, s[i * 32] * v);
}

__global__ void ln_kernel(const float* __restrict__ h,
                          const float* __restrict__ g,
                          const float* __restrict__ b,
                          float* __restrict__ out) {
    int n = blockIdx.x * 8 + (threadIdx.x >> 5);
    if (n >= NN) return;
    int lane = threadIdx.x & 31;
    const float* r = h + (size_t)n * CC;
    float v[4];
    float s = 0.f;
#pragma unroll
    for (int i = 0; i < 4; i++) { v[i] = r[lane + i * 32]; s += v[i]; }
#pragma unroll
    for (int o = 16; o; o >>= 1) s += __shfl_xor_sync(0xffffffffu, s, o);
    float mu = s * (1.f / 128.f);
    float q = 0.f;
#pragma unroll
    for (int i = 0; i < 4; i++) { float d = v[i] - mu; q = fmaf(d, d, q); }
#pragma unroll
    for (int o = 16; o; o >>= 1) q += __shfl_xor_sync(0xffffffffu, q, o);
    float inv = rsqrtf(q * (1.f / 128.f) + 1e-5f);
#pragma unroll
    for (int i = 0; i < 4; i++) {
        int c = lane + i * 32;
        out[(size_t)n * CC + c] = fmaf((v[i] - mu) * inv, g[c], b[c]);
    }
}

// ---------------------------------------------------------------------------
extern "C" void kernel_launch(void* const* d_in, const int* in_sizes, int n_in,
                              void* d_out, int out_size) {
    const float* x   = (const float*)d_in[0];
    const int*   ei  = (const int*)d_in[1];
    const float* ev  = (const float*)d_in[2];
    const float* lw1 = (const float*)d_in[3];
    const float* lb1 = (const float*)d_in[4];
    const float* lw2 = (const float*)d_in[5];
    const float* lb2 = (const float*)d_in[6];
    const float* sw  = (const float*)d_in[7];
    const float* sb  = (const float*)d_in[8];
    const float* nw  = (const float*)d_in[9];
    const float* nbw = (const float*)d_in[10];
    const float* gw1 = (const float*)d_in[11];
    const float* gb1 = (const float*)d_in[12];
    const float* gw2 = (const float*)d_in[13];
    const float* gb2 = (const float*)d_in[14];
    const float* ng  = (const float*)d_in[15];
    const float* nbt = (const float*)d_in[16];
    float* out = (float*)d_out;

    float *h, *nbuf, *selfb, *aggr, *u;
    cudaGetSymbolAddress((void**)&h, g_h);
    cudaGetSymbolAddress((void**)&nbuf, g_nb);
    cudaGetSymbolAddress((void**)&selfb, g_self);
    cudaGetSymbolAddress((void**)&aggr, g_aggr);
    cudaGetSymbolAddress((void**)&u, g_u);
    __nv_bfloat16 *wbh, *wbl;
    cudaGetSymbolAddress((void**)&wbh, g_wbh);
    cudaGetSymbolAddress((void**)&wbl, g_wbl);

    cudaFuncSetAttribute(gemm_mma<0, 0>, cudaFuncAttributeMaxDynamicSharedMemorySize, SM_TOTAL);
    cudaFuncSetAttribute(gemm_mma<1, 0>, cudaFuncAttributeMaxDynamicSharedMemorySize, SM_TOTAL);
    cudaFuncSetAttribute(gemm_mma<0, 1>, cudaFuncAttributeMaxDynamicSharedMemorySize, SM_TOTAL);

    const int GB = (NN + 127) / 128;  // 782 tiles

    // Pre-split weights (bf16 hi/lo)
    wconv_kernel<<<(WSLOTS * 16384 + 255) / 256, 256>>>(lw2, sw, nw, gw1, gw2);

    // Lift
    lift_hidden_kernel<<<(NN * CC + 255) / 256, 256>>>(x, lw1, lb1);
    gemm_mma<0, 0><<<GB, 256, SM_TOTAL>>>(u, nullptr, wbh, wbl, lb2, nullptr, h, 1);

    for (int l = 0; l < 2; l++) {
        const __nv_bfloat16* nh = wbh + (size_t)(1 + 5 * l) * 16384;
        const __nv_bfloat16* nl = wbl + (size_t)(1 + 5 * l) * 16384;
        const __nv_bfloat16* sh = wbh + (size_t)(2 + 5 * l) * 16384;
        const __nv_bfloat16* sl = wbl + (size_t)(2 + 5 * l) * 16384;
        const __nv_bfloat16* g1h = wbh + (size_t)(3 + 5 * l) * 16384;
        const __nv_bfloat16* g1l = wbl + (size_t)(3 + 5 * l) * 16384;
        const __nv_bfloat16* g2h = wbh + (size_t)(5 + 5 * l) * 16384;
        const __nv_bfloat16* g2l = wbl + (size_t)(5 + 5 * l) * 16384;

        // neighbor = h @ Wn + bn
        gemm_mma<0, 0><<<GB, 256, SM_TOTAL>>>(h, nullptr, nh, nl, nbw + l * CC, nullptr, nbuf, 1);
        // aggr = scatter_add(neighbor[col] * ev, row)
        zero_aggr_kernel<<<NN * CC / 4 / 256 + 1, 256>>>();
        edge_kernel<<<EE / 8, 256>>>(ei, ev);
        // self_f = h @ Ws + bs
        gemm_mma<0, 0><<<GB, 256, SM_TOTAL>>>(h, nullptr, sh, sl, sb + l * CC, nullptr, selfb, 1);
        // u = gelu([self_f, aggr] @ Wg1 + bg1)   (K = 256 via 2 chunks)
        gemm_mma<1, 0><<<GB, 256, SM_TOTAL>>>(selfb, aggr, g1h, g1l, gb1 + l * CC, nullptr, u, 2);
        // h = h + u @ Wg2 + bg2
        gemm_mma<0, 1><<<GB, 256, SM_TOTAL>>>(u, nullptr, g2h, g2l, gb2 + l * CC, h, h, 1);
    }

    ln_kernel<<<(NN + 7) / 8, 256>>>(h, ng, nbt, out);
}

// round 4
// speedup vs baseline: 2.2971x; 1.6876x over previous
#include <cuda_runtime.h>
#include <cuda_bf16.h>
#include <math.h>
#include <stdint.h>

#define NN 100000
#define EE 1600000
#define CC 128
#define SCAN_BLOCKS ((NN + 255) / 256)   // 391

// ---------------------------------------------------------------------------
// Scratch (allocation-free rule: __device__ globals)
// ---------------------------------------------------------------------------
__device__ float g_h[(size_t)NN * CC];
__device__ float g_nb[(size_t)NN * CC];
__device__ float g_self[(size_t)NN * CC];
__device__ float g_aggr[(size_t)NN * CC];
__device__ float g_u[(size_t)NN * CC];

// CSR scratch
__device__ int   g_cnt[NN];
__device__ int   g_rowstart[NN + 1];
__device__ int   g_cursor[NN];
__device__ int   g_bsum[SCAN_BLOCKS];
__device__ int   g_boff[SCAN_BLOCKS];
__device__ int   g_ecol[EE];
__device__ float g_eval[EE];

// Pre-converted bf16 weight tiles (hi/lo split), layout [slot][n][k]
#define WSLOTS 11
__device__ __nv_bfloat16 g_wbh[(size_t)WSLOTS * 16384];
__device__ __nv_bfloat16 g_wbl[(size_t)WSLOTS * 16384];

__device__ __forceinline__ float gelu_f(float v) {
    return 0.5f * v * (1.0f + erff(v * 0.7071067811865475f));
}

// ---------------------------------------------------------------------------
// mma.sync helpers (arch-generic PTX, HMMA on sm_103)
// ---------------------------------------------------------------------------
__device__ __forceinline__ void ldsm_x4(uint32_t* r, uint32_t addr) {
    asm volatile("ldmatrix.sync.aligned.m8n8.x4.shared.b16 {%0,%1,%2,%3}, [%4];"
                 : "=r"(r[0]), "=r"(r[1]), "=r"(r[2]), "=r"(r[3]) : "r"(addr));
}
__device__ __forceinline__ void mma16816(float* d, const uint32_t* a, const uint32_t* b) {
    asm volatile(
        "mma.sync.aligned.m16n8k16.row.col.f32.bf16.bf16.f32 "
        "{%0,%1,%2,%3}, {%4,%5,%6,%7}, {%8,%9}, {%0,%1,%2,%3};"
        : "+f"(d[0]), "+f"(d[1]), "+f"(d[2]), "+f"(d[3])
        : "r"(a[0]), "r"(a[1]), "r"(a[2]), "r"(a[3]), "r"(b[0]), "r"(b[1]));
}

// ---------------------------------------------------------------------------
// Weight conversion: fp32 W[K,N] -> bf16 hi/lo B[N,K]
// ---------------------------------------------------------------------------
__global__ void wconv_kernel(const float* __restrict__ lw2,
                             const float* __restrict__ sw,
                             const float* __restrict__ nw,
                             const float* __restrict__ gw1,
                             const float* __restrict__ gw2) {
    int idx = blockIdx.x * blockDim.x + threadIdx.x;
    if (idx >= WSLOTS * 16384) return;
    int slot = idx >> 14;
    int within = idx & 16383;
    int n = within >> 7;
    int k = within & 127;
    const float* src;
    if (slot == 0) {
        src = lw2 + k * 128 + n;
    } else {
        int l = (slot - 1) / 5, j = (slot - 1) % 5;
        if (j == 0)      src = nw  + (size_t)l * 16384 + k * 128 + n;
        else if (j == 1) src = sw  + (size_t)l * 16384 + k * 128 + n;
        else if (j == 2) src = gw1 + (size_t)l * 32768 + k * 128 + n;
        else if (j == 3) src = gw1 + (size_t)l * 32768 + 16384 + k * 128 + n;
        else             src = gw2 + (size_t)l * 16384 + k * 128 + n;
    }
    float v = *src;
    __nv_bfloat16 hi = __float2bfloat16(v);
    __nv_bfloat16 lo = __float2bfloat16(v - __bfloat162float(hi));
    g_wbh[idx] = hi;
    g_wbl[idx] = lo;
}

// ---------------------------------------------------------------------------
// HMMA GEMM: Out[M x 128] = act(A @ W + bias) (+ residual)
// ---------------------------------------------------------------------------
#define ROWB 272
#define SM_AH 0
#define SM_AL (128 * ROWB)
#define SM_BH (2 * 128 * ROWB)
#define SM_BL (3 * 128 * ROWB)
#define SM_TOTAL (4 * 128 * ROWB)   // 139264 bytes

template <int GELU, int RESID>
__global__ void __launch_bounds__(256, 1) gemm_mma(
    const float* __restrict__ A0, const float* __restrict__ A1,
    const __nv_bfloat16* __restrict__ Bh, const __nv_bfloat16* __restrict__ Bl,
    const float* __restrict__ bias, const float* __restrict__ R,
    float* __restrict__ Out, int kchunks) {
    extern __shared__ __align__(16) char smem[];
    const uint32_t sb = (uint32_t)__cvta_generic_to_shared(smem);
    const int tid = threadIdx.x;
    const int wid = tid >> 5;
    const int lane = tid & 31;
    const int warp_m = wid >> 1;
    const int warp_n = wid & 1;
    const int m0 = blockIdx.x * 128;

    float acc[2][8][4];
#pragma unroll
    for (int mi = 0; mi < 2; mi++)
#pragma unroll
        for (int nt = 0; nt < 8; nt++)
#pragma unroll
            for (int e = 0; e < 4; e++) acc[mi][nt][e] = 0.0f;

    const uint32_t a_lane = (uint32_t)(((lane & 7) + ((lane >> 3) & 1) * 8) * ROWB +
                                       (lane >> 4) * 16);
    const uint32_t b_lane = (uint32_t)(((lane & 7) + ((lane >> 4) & 1) * 8) * ROWB +
                                       ((lane >> 3) & 1) * 16);

    for (int c = 0; c < kchunks; c++) {
        const float* A = (c == 0) ? A0 : A1;
        const uint4* bhp = (const uint4*)(Bh + (size_t)c * 16384);
        const uint4* blp = (const uint4*)(Bl + (size_t)c * 16384);

        if (c) __syncthreads();

#pragma unroll
        for (int i = 0; i < 8; i++) {
            int ci = tid + i * 256;
            int row = ci >> 4, ch = ci & 15;
            uint32_t off = (uint32_t)(row * ROWB + ch * 16);
            *(uint4*)(smem + SM_BH + off) = bhp[ci];
            *(uint4*)(smem + SM_BL + off) = blp[ci];
        }
#pragma unroll
        for (int i = 0; i < 8; i++) {
            int ci = tid + i * 256;
            int row = ci >> 4, ch = ci & 15;
            int gm = m0 + row;
            float v[8];
            if (gm < NN) {
                float4 a = *(const float4*)(A + (size_t)gm * 128 + ch * 8);
                float4 b = *(const float4*)(A + (size_t)gm * 128 + ch * 8 + 4);
                v[0] = a.x; v[1] = a.y; v[2] = a.z; v[3] = a.w;
                v[4] = b.x; v[5] = b.y; v[6] = b.z; v[7] = b.w;
            } else {
#pragma unroll
                for (int e = 0; e < 8; e++) v[e] = 0.0f;
            }
            __align__(16) __nv_bfloat16 h8[8], l8[8];
#pragma unroll
            for (int e = 0; e < 8; e++) {
                h8[e] = __float2bfloat16(v[e]);
                l8[e] = __float2bfloat16(v[e] - __bfloat162float(h8[e]));
            }
            uint32_t off = (uint32_t)(row * ROWB + ch * 16);
            *(uint4*)(smem + SM_AH + off) = *(uint4*)h8;
            *(uint4*)(smem + SM_AL + off) = *(uint4*)l8;
        }
        __syncthreads();

#pragma unroll
        for (int t = 0; t < 3; t++) {
            const uint32_t abase = sb + ((t < 2) ? SM_AH : SM_AL) +
                                   (uint32_t)(warp_m * 32 * ROWB) + a_lane;
            const uint32_t bbase = sb + ((t == 1) ? SM_BL : SM_BH) +
                                   (uint32_t)(warp_n * 64 * ROWB) + b_lane;
#pragma unroll
            for (int ks = 0; ks < 8; ks++) {
                uint32_t af[2][4];
                ldsm_x4(af[0], abase + ks * 32);
                ldsm_x4(af[1], abase + ks * 32 + 16 * ROWB);
                uint32_t bf[4][4];
#pragma unroll
                for (int np = 0; np < 4; np++)
                    ldsm_x4(bf[np], bbase + ks * 32 + np * 16 * ROWB);
#pragma unroll
                for (int mi = 0; mi < 2; mi++)
#pragma unroll
                    for (int nt = 0; nt < 8; nt++) {
                        uint32_t bb[2] = { bf[nt >> 1][(nt & 1) * 2],
                                           bf[nt >> 1][(nt & 1) * 2 + 1] };
                        mma16816(acc[mi][nt], af[mi], bb);
                    }
            }
        }
    }

#pragma unroll
    for (int mi = 0; mi < 2; mi++) {
        int r0 = m0 + warp_m * 32 + mi * 16 + (lane >> 2);
#pragma unroll
        for (int half = 0; half < 2; half++) {
            int r = r0 + half * 8;
            if (r >= NN) continue;
            float* orow = Out + (size_t)r * 128;
            const float* rrow = RESID ? (R + (size_t)r * 128) : nullptr;
#pragma unroll
            for (int nt = 0; nt < 8; nt++) {
                int col = warp_n * 64 + nt * 8 + (lane & 3) * 2;
                float x0 = acc[mi][nt][half * 2 + 0] + __ldg(bias + col);
                float x1 = acc[mi][nt][half * 2 + 1] + __ldg(bias + col + 1);
                if (GELU) { x0 = gelu_f(x0); x1 = gelu_f(x1); }
                if (RESID) {
                    float2 rr = *(const float2*)(rrow + col);
                    x0 += rr.x; x1 += rr.y;
                }
                *(float2*)(orow + col) = make_float2(x0, x1);
            }
        }
    }
}

// ---------------------------------------------------------------------------
// CSR build: count -> scan -> fill  (graph static per launch; build once)
// ---------------------------------------------------------------------------
__global__ void k_zero_cnt() {
    int i = blockIdx.x * blockDim.x + threadIdx.x;
    if (i < NN) g_cnt[i] = 0;
}
__global__ void k_count(const int* __restrict__ ei) {
    int e = blockIdx.x * blockDim.x + threadIdx.x;
    if (e < EE) atomicAdd(&g_cnt[ei[e]], 1);
}
__global__ void k_blocksum() {
    __shared__ int sh[256];
    int i = blockIdx.x * 256 + threadIdx.x;
    int v = (i < NN) ? g_cnt[i] : 0;
    sh[threadIdx.x] = v;
    __syncthreads();
    for (int s = 128; s; s >>= 1) {
        if (threadIdx.x < s) sh[threadIdx.x] += sh[threadIdx.x + s];
        __syncthreads();
    }
    if (threadIdx.x == 0) g_bsum[blockIdx.x] = sh[0];
}
__global__ void k_scan_bsum() {
    // single block, 512 threads, exclusive scan over SCAN_BLOCKS entries
    __shared__ int sh[512];
    int t = threadIdx.x;
    sh[t] = (t < SCAN_BLOCKS) ? g_bsum[t] : 0;
    __syncthreads();
    // inclusive scan (Hillis-Steele)
    for (int off = 1; off < 512; off <<= 1) {
        int v = (t >= off) ? sh[t - off] : 0;
        __syncthreads();
        sh[t] += v;
        __syncthreads();
    }
    if (t < SCAN_BLOCKS) g_boff[t] = sh[t] - g_bsum[t];  // exclusive
}
__global__ void k_rowstart() {
    __shared__ int sh[256];
    int i = blockIdx.x * 256 + threadIdx.x;
    int v = (i < NN) ? g_cnt[i] : 0;
    sh[threadIdx.x] = v;
    __syncthreads();
    // inclusive scan within block
    for (int off = 1; off < 256; off <<= 1) {
        int u = (threadIdx.x >= off) ? sh[threadIdx.x - off] : 0;
        __syncthreads();
        sh[threadIdx.x] += u;
        __syncthreads();
    }
    if (i < NN) {
        int excl = sh[threadIdx.x] - v + g_boff[blockIdx.x];
        g_rowstart[i] = excl;
        g_cursor[i] = excl;
        if (i == NN - 1) g_rowstart[NN] = excl + v;
    }
}
__global__ void k_fill(const int* __restrict__ ei, const float* __restrict__ ev) {
    int e = blockIdx.x * blockDim.x + threadIdx.x;
    if (e >= EE) return;
    int row = ei[e];
    int pos = atomicAdd(&g_cursor[row], 1);
    g_ecol[pos] = ei[EE + e];
    g_eval[pos] = ev[e];
}

// ---------------------------------------------------------------------------
// Pull aggregation: one warp per row. aggr[row] = sum_j ev_j * nb[col_j].
// No atomics, no zero-pass.
// ---------------------------------------------------------------------------
__global__ void k_aggr() {
    int r = blockIdx.x * 8 + (threadIdx.x >> 5);
    if (r >= NN) return;
    int lane = threadIdx.x & 31;
    int s = g_rowstart[r];
    int epos_end = g_rowstart[r + 1];
    float acc0 = 0.f, acc1 = 0.f, acc2 = 0.f, acc3 = 0.f;
    for (int j = s; j < epos_end; j++) {
        int c = __ldg(&g_ecol[j]);
        float v = __ldg(&g_eval[j]);
        const float* srow = g_nb + (size_t)c * CC + lane;
        acc0 = fmaf(__ldg(srow),      v, acc0);
        acc1 = fmaf(__ldg(srow + 32), v, acc1);
        acc2 = fmaf(__ldg(srow + 64), v, acc2);
        acc3 = fmaf(__ldg(srow + 96), v, acc3);
    }
    float* d = g_aggr + (size_t)r * CC + lane;
    d[0]  = acc0;
    d[32] = acc1;
    d[64] = acc2;
    d[96] = acc3;
}

// ---------------------------------------------------------------------------
// Lift stage 1
// ---------------------------------------------------------------------------
__global__ void lift_hidden_kernel(const float* __restrict__ x,
                                   const float* __restrict__ w1,
                                   const float* __restrict__ b1) {
    int idx = blockIdx.x * blockDim.x + threadIdx.x;
    if (idx >= NN * CC) return;
    int n = idx >> 7;
    int c = idx & 127;
    const float* xr = x + (size_t)n * 9 + 3;
    float acc = b1[c];
#pragma unroll
    for (int i = 0; i < 6; i++)
        acc = fmaf(xr[i], w1[i * CC + c], acc);
    g_u[idx] = gelu_f(acc);
}

__global__ void ln_kernel(const float* __restrict__ h,
                          const float* __restrict__ g,
                          const float* __restrict__ b,
                          float* __restrict__ out) {
    int n = blockIdx.x * 8 + (threadIdx.x >> 5);
    if (n >= NN) return;
    int lane = threadIdx.x & 31;
    const float* r = h + (size_t)n * CC;
    float v[4];
    float s = 0.f;
#pragma unroll
    for (int i = 0; i < 4; i++) { v[i] = r[lane + i * 32]; s += v[i]; }
#pragma unroll
    for (int o = 16; o; o >>= 1) s += __shfl_xor_sync(0xffffffffu, s, o);
    float mu = s * (1.f / 128.f);
    float q = 0.f;
#pragma unroll
    for (int i = 0; i < 4; i++) { float d = v[i] - mu; q = fmaf(d, d, q); }
#pragma unroll
    for (int o = 16; o; o >>= 1) q += __shfl_xor_sync(0xffffffffu, q, o);
    float inv = rsqrtf(q * (1.f / 128.f) + 1e-5f);
#pragma unroll
    for (int i = 0; i < 4; i++) {
        int c = lane + i * 32;
        out[(size_t)n * CC + c] = fmaf((v[i] - mu) * inv, g[c], b[c]);
    }
}

// ---------------------------------------------------------------------------
extern "C" void kernel_launch(void* const* d_in, const int* in_sizes, int n_in,
                              void* d_out, int out_size) {
    const float* x   = (const float*)d_in[0];
    const int*   ei  = (const int*)d_in[1];
    const float* ev  = (const float*)d_in[2];
    const float* lw1 = (const float*)d_in[3];
    const float* lb1 = (const float*)d_in[4];
    const float* lw2 = (const float*)d_in[5];
    const float* lb2 = (const float*)d_in[6];
    const float* sw  = (const float*)d_in[7];
    const float* sb  = (const float*)d_in[8];
    const float* nw  = (const float*)d_in[9];
    const float* nbw = (const float*)d_in[10];
    const float* gw1 = (const float*)d_in[11];
    const float* gb1 = (const float*)d_in[12];
    const float* gw2 = (const float*)d_in[13];
    const float* gb2 = (const float*)d_in[14];
    const float* ng  = (const float*)d_in[15];
    const float* nbt = (const float*)d_in[16];
    float* out = (float*)d_out;

    float *h, *nbuf, *selfb, *aggr, *u;
    cudaGetSymbolAddress((void**)&h, g_h);
    cudaGetSymbolAddress((void**)&nbuf, g_nb);
    cudaGetSymbolAddress((void**)&selfb, g_self);
    cudaGetSymbolAddress((void**)&aggr, g_aggr);
    cudaGetSymbolAddress((void**)&u, g_u);
    __nv_bfloat16 *wbh, *wbl;
    cudaGetSymbolAddress((void**)&wbh, g_wbh);
    cudaGetSymbolAddress((void**)&wbl, g_wbl);

    cudaFuncSetAttribute(gemm_mma<0, 0>, cudaFuncAttributeMaxDynamicSharedMemorySize, SM_TOTAL);
    cudaFuncSetAttribute(gemm_mma<1, 0>, cudaFuncAttributeMaxDynamicSharedMemorySize, SM_TOTAL);
    cudaFuncSetAttribute(gemm_mma<0, 1>, cudaFuncAttributeMaxDynamicSharedMemorySize, SM_TOTAL);

    const int GB = (NN + 127) / 128;

    // Pre-split weights + CSR build (once per launch)
    wconv_kernel<<<(WSLOTS * 16384 + 255) / 256, 256>>>(lw2, sw, nw, gw1, gw2);
    k_zero_cnt<<<SCAN_BLOCKS, 256>>>();
    k_count<<<(EE + 255) / 256, 256>>>(ei);
    k_blocksum<<<SCAN_BLOCKS, 256>>>();
    k_scan_bsum<<<1, 512>>>();
    k_rowstart<<<SCAN_BLOCKS, 256>>>();
    k_fill<<<(EE + 255) / 256, 256>>>(ei, ev);

    // Lift
    lift_hidden_kernel<<<(NN * CC + 255) / 256, 256>>>(x, lw1, lb1);
    gemm_mma<0, 0><<<GB, 256, SM_TOTAL>>>(u, nullptr, wbh, wbl, lb2, nullptr, h, 1);

    for (int l = 0; l < 2; l++) {
        const __nv_bfloat16* nh = wbh + (size_t)(1 + 5 * l) * 16384;
        const __nv_bfloat16* nl = wbl + (size_t)(1 + 5 * l) * 16384;
        const __nv_bfloat16* sh = wbh + (size_t)(2 + 5 * l) * 16384;
        const __nv_bfloat16* sl = wbl + (size_t)(2 + 5 * l) * 16384;
        const __nv_bfloat16* g1h = wbh + (size_t)(3 + 5 * l) * 16384;
        const __nv_bfloat16* g1l = wbl + (size_t)(3 + 5 * l) * 16384;
        const __nv_bfloat16* g2h = wbh + (size_t)(5 + 5 * l) * 16384;
        const __nv_bfloat16* g2l = wbl + (size_t)(5 + 5 * l) * 16384;

        // neighbor = h @ Wn + bn
        gemm_mma<0, 0><<<GB, 256, SM_TOTAL>>>(h, nullptr, nh, nl, nbw + l * CC, nullptr, nbuf, 1);
        // aggr[row] = sum ev * neighbor[col]  (pull, no atomics)
        k_aggr<<<(NN + 7) / 8, 256>>>();
        // self_f = h @ Ws + bs
        gemm_mma<0, 0><<<GB, 256, SM_TOTAL>>>(h, nullptr, sh, sl, sb + l * CC, nullptr, selfb, 1);
        // u = gelu([self_f, aggr] @ Wg1 + bg1)
        gemm_mma<1, 0><<<GB, 256, SM_TOTAL>>>(selfb, aggr, g1h, g1l, gb1 + l * CC, nullptr, u, 2);
        // h = h + u @ Wg2 + bg2
        gemm_mma<0, 1><<<GB, 256, SM_TOTAL>>>(u, nullptr, g2h, g2l, gb2 + l * CC, h, h, 1);
    }

    ln_kernel<<<(NN + 7) / 8, 256>>>(h, ng, nbt, out);
}

// round 5
// speedup vs baseline: 2.5535x; 1.1116x over previous
#include <cuda_runtime.h>
#include <cuda_bf16.h>
#include <math.h>
#include <stdint.h>

#define NN 100000
#define EE 1600000
#define CC 128
#define SCAN_BLOCKS ((NN + 255) / 256)   // 391

// ---------------------------------------------------------------------------
// Scratch (allocation-free rule: __device__ globals)
// ---------------------------------------------------------------------------
__device__ float g_h[(size_t)NN * CC];
__device__ float g_nb[(size_t)NN * CC];
__device__ float g_self[(size_t)NN * CC];
__device__ float g_aggr[(size_t)NN * CC];
__device__ float g_u[(size_t)NN * CC];

// CSR scratch
__device__ int   g_cnt[NN];
__device__ int   g_rowstart[NN + 1];
__device__ int   g_cursor[NN];
__device__ int   g_bsum[SCAN_BLOCKS];
__device__ int   g_boff[SCAN_BLOCKS];
__device__ int   g_ecol[EE];
__device__ float g_eval[EE];

// Pre-converted bf16 weight tiles (hi/lo split), layout [slot][n][k]
#define WSLOTS 11
__device__ __nv_bfloat16 g_wbh[(size_t)WSLOTS * 16384];
__device__ __nv_bfloat16 g_wbl[(size_t)WSLOTS * 16384];

__device__ __forceinline__ float gelu_f(float v) {
    return 0.5f * v * (1.0f + erff(v * 0.7071067811865475f));
}

// ---------------------------------------------------------------------------
// mma.sync helpers (arch-generic PTX, HMMA on sm_103)
// ---------------------------------------------------------------------------
__device__ __forceinline__ void ldsm_x4(uint32_t* r, uint32_t addr) {
    asm volatile("ldmatrix.sync.aligned.m8n8.x4.shared.b16 {%0,%1,%2,%3}, [%4];"
                 : "=r"(r[0]), "=r"(r[1]), "=r"(r[2]), "=r"(r[3]) : "r"(addr));
}
__device__ __forceinline__ void mma16816(float* d, const uint32_t* a, const uint32_t* b) {
    asm volatile(
        "mma.sync.aligned.m16n8k16.row.col.f32.bf16.bf16.f32 "
        "{%0,%1,%2,%3}, {%4,%5,%6,%7}, {%8,%9}, {%0,%1,%2,%3};"
        : "+f"(d[0]), "+f"(d[1]), "+f"(d[2]), "+f"(d[3])
        : "r"(a[0]), "r"(a[1]), "r"(a[2]), "r"(a[3]), "r"(b[0]), "r"(b[1]));
}

// ---------------------------------------------------------------------------
// Smem layout for GEMM kernels
// ---------------------------------------------------------------------------
#define ROWB 272
#define SM_AH 0
#define SM_AL (128 * ROWB)
#define SM_BH (2 * 128 * ROWB)
#define SM_BL (3 * 128 * ROWB)
#define SM_TOTAL (4 * 128 * ROWB)   // 139264 bytes

// 3-term bf16-split MMA over a full staged 128-K chunk.
// aH/aL/bH/bL are per-warp, per-lane ldmatrix base addresses.
__device__ __forceinline__ void mma_chunk(float acc[2][8][4], uint32_t aH,
                                          uint32_t aL, uint32_t bH, uint32_t bL) {
#pragma unroll
    for (int ks = 0; ks < 8; ks++) {
        uint32_t ah[2][4], al[2][4], bh[4][4], bl[4][4];
        ldsm_x4(ah[0], aH + ks * 32);
        ldsm_x4(ah[1], aH + ks * 32 + 16 * ROWB);
        ldsm_x4(al[0], aL + ks * 32);
        ldsm_x4(al[1], aL + ks * 32 + 16 * ROWB);
#pragma unroll
        for (int np = 0; np < 4; np++) {
            ldsm_x4(bh[np], bH + ks * 32 + np * 16 * ROWB);
            ldsm_x4(bl[np], bL + ks * 32 + np * 16 * ROWB);
        }
#pragma unroll
        for (int mi = 0; mi < 2; mi++)
#pragma unroll
            for (int nt = 0; nt < 8; nt++) {
                uint32_t bbh[2] = { bh[nt >> 1][(nt & 1) * 2], bh[nt >> 1][(nt & 1) * 2 + 1] };
                uint32_t bbl[2] = { bl[nt >> 1][(nt & 1) * 2], bl[nt >> 1][(nt & 1) * 2 + 1] };
                mma16816(acc[mi][nt], ah[mi], bbh);
                mma16816(acc[mi][nt], ah[mi], bbl);
                mma16816(acc[mi][nt], al[mi], bbh);
            }
    }
}

// Stage a 128x128 fp32 A chunk as bf16 hi/lo into smem (cooperative, 256 thr).
__device__ __forceinline__ void stage_A(char* smem, const float* __restrict__ A,
                                        int m0, int tid) {
#pragma unroll
    for (int i = 0; i < 8; i++) {
        int ci = tid + i * 256;
        int row = ci >> 4, ch = ci & 15;
        int gm = m0 + row;
        float v[8];
        if (gm < NN) {
            float4 a = *(const float4*)(A + (size_t)gm * 128 + ch * 8);
            float4 b = *(const float4*)(A + (size_t)gm * 128 + ch * 8 + 4);
            v[0] = a.x; v[1] = a.y; v[2] = a.z; v[3] = a.w;
            v[4] = b.x; v[5] = b.y; v[6] = b.z; v[7] = b.w;
        } else {
#pragma unroll
            for (int e = 0; e < 8; e++) v[e] = 0.0f;
        }
        __align__(16) __nv_bfloat16 h8[8], l8[8];
#pragma unroll
        for (int e = 0; e < 8; e++) {
            h8[e] = __float2bfloat16(v[e]);
            l8[e] = __float2bfloat16(v[e] - __bfloat162float(h8[e]));
        }
        uint32_t off = (uint32_t)(row * ROWB + ch * 16);
        *(uint4*)(smem + SM_AH + off) = *(uint4*)h8;
        *(uint4*)(smem + SM_AL + off) = *(uint4*)l8;
    }
}

__device__ __forceinline__ void stage_B(char* smem, const __nv_bfloat16* __restrict__ Bh,
                                        const __nv_bfloat16* __restrict__ Bl, int tid) {
    const uint4* bhp = (const uint4*)Bh;
    const uint4* blp = (const uint4*)Bl;
#pragma unroll
    for (int i = 0; i < 8; i++) {
        int ci = tid + i * 256;
        int row = ci >> 4, ch = ci & 15;
        uint32_t off = (uint32_t)(row * ROWB + ch * 16);
        *(uint4*)(smem + SM_BH + off) = bhp[ci];
        *(uint4*)(smem + SM_BL + off) = blp[ci];
    }
}

// Epilogue: acc (+bias, act, +resid) -> Out rows.
template <int GELU, int RESID>
__device__ __forceinline__ void epilogue(float acc[2][8][4], const float* __restrict__ bias,
                                         const float* __restrict__ R, float* __restrict__ Out,
                                         int m0, int warp_m, int warp_n, int lane) {
    float b0[8], b1[8];
#pragma unroll
    for (int nt = 0; nt < 8; nt++) {
        int col = warp_n * 64 + nt * 8 + (lane & 3) * 2;
        b0[nt] = __ldg(bias + col);
        b1[nt] = __ldg(bias + col + 1);
    }
#pragma unroll
    for (int mi = 0; mi < 2; mi++) {
        int r0 = m0 + warp_m * 32 + mi * 16 + (lane >> 2);
#pragma unroll
        for (int half = 0; half < 2; half++) {
            int r = r0 + half * 8;
            if (r >= NN) continue;
            float* orow = Out + (size_t)r * 128;
            const float* rrow = RESID ? (R + (size_t)r * 128) : nullptr;
#pragma unroll
            for (int nt = 0; nt < 8; nt++) {
                int col = warp_n * 64 + nt * 8 + (lane & 3) * 2;
                float x0 = acc[mi][nt][half * 2 + 0] + b0[nt];
                float x1 = acc[mi][nt][half * 2 + 1] + b1[nt];
                if (GELU) { x0 = gelu_f(x0); x1 = gelu_f(x1); }
                if (RESID) {
                    float2 rr = *(const float2*)(rrow + col);
                    x0 += rr.x; x1 += rr.y;
                }
                *(float2*)(orow + col) = make_float2(x0, x1);
            }
        }
    }
}

// ---------------------------------------------------------------------------
// Generic GEMM: Out = act(A @ W + bias) (+ resid). kchunks in {1,2}.
// ---------------------------------------------------------------------------
template <int GELU, int RESID>
__global__ void __launch_bounds__(256, 1) gemm_mma(
    const float* __restrict__ A0, const float* __restrict__ A1,
    const __nv_bfloat16* __restrict__ Bh, const __nv_bfloat16* __restrict__ Bl,
    const float* __restrict__ bias, const float* __restrict__ R,
    float* __restrict__ Out, int kchunks) {
    extern __shared__ __align__(16) char smem[];
    const uint32_t sb = (uint32_t)__cvta_generic_to_shared(smem);
    const int tid = threadIdx.x;
    const int lane = tid & 31;
    const int warp_m = (tid >> 5) >> 1;
    const int warp_n = (tid >> 5) & 1;
    const int m0 = blockIdx.x * 128;

    float acc[2][8][4];
#pragma unroll
    for (int mi = 0; mi < 2; mi++)
#pragma unroll
        for (int nt = 0; nt < 8; nt++)
#pragma unroll
            for (int e = 0; e < 4; e++) acc[mi][nt][e] = 0.0f;

    const uint32_t a_lane = (uint32_t)(((lane & 7) + ((lane >> 3) & 1) * 8) * ROWB +
                                       (lane >> 4) * 16);
    const uint32_t b_lane = (uint32_t)(((lane & 7) + ((lane >> 4) & 1) * 8) * ROWB +
                                       ((lane >> 3) & 1) * 16);
    const uint32_t aH = sb + SM_AH + (uint32_t)(warp_m * 32 * ROWB) + a_lane;
    const uint32_t aL = sb + SM_AL + (uint32_t)(warp_m * 32 * ROWB) + a_lane;
    const uint32_t bH = sb + SM_BH + (uint32_t)(warp_n * 64 * ROWB) + b_lane;
    const uint32_t bL = sb + SM_BL + (uint32_t)(warp_n * 64 * ROWB) + b_lane;

    for (int c = 0; c < kchunks; c++) {
        if (c) __syncthreads();
        stage_B(smem, Bh + (size_t)c * 16384, Bl + (size_t)c * 16384, tid);
        stage_A(smem, (c == 0) ? A0 : A1, m0, tid);
        __syncthreads();
        mma_chunk(acc, aH, aL, bH, bL);
    }
    epilogue<GELU, RESID>(acc, bias, R, Out, m0, warp_m, warp_n, lane);
}

// ---------------------------------------------------------------------------
// Fused neighbor+self GEMM: stage A (= h) once, run two weight sets.
// ---------------------------------------------------------------------------
__global__ void __launch_bounds__(256, 1) gemm_ns(
    const float* __restrict__ A,
    const __nv_bfloat16* __restrict__ Bnh, const __nv_bfloat16* __restrict__ Bnl,
    const float* __restrict__ bn, float* __restrict__ OutN,
    const __nv_bfloat16* __restrict__ Bsh, const __nv_bfloat16* __restrict__ Bsl,
    const float* __restrict__ bs, float* __restrict__ OutS) {
    extern __shared__ __align__(16) char smem[];
    const uint32_t sb = (uint32_t)__cvta_generic_to_shared(smem);
    const int tid = threadIdx.x;
    const int lane = tid & 31;
    const int warp_m = (tid >> 5) >> 1;
    const int warp_n = (tid >> 5) & 1;
    const int m0 = blockIdx.x * 128;

    const uint32_t a_lane = (uint32_t)(((lane & 7) + ((lane >> 3) & 1) * 8) * ROWB +
                                       (lane >> 4) * 16);
    const uint32_t b_lane = (uint32_t)(((lane & 7) + ((lane >> 4) & 1) * 8) * ROWB +
                                       ((lane >> 3) & 1) * 16);
    const uint32_t aH = sb + SM_AH + (uint32_t)(warp_m * 32 * ROWB) + a_lane;
    const uint32_t aL = sb + SM_AL + (uint32_t)(warp_m * 32 * ROWB) + a_lane;
    const uint32_t bH = sb + SM_BH + (uint32_t)(warp_n * 64 * ROWB) + b_lane;
    const uint32_t bL = sb + SM_BL + (uint32_t)(warp_n * 64 * ROWB) + b_lane;

    stage_B(smem, Bnh, Bnl, tid);
    stage_A(smem, A, m0, tid);
    __syncthreads();

    float acc[2][8][4];
#pragma unroll
    for (int mi = 0; mi < 2; mi++)
#pragma unroll
        for (int nt = 0; nt < 8; nt++)
#pragma unroll
            for (int e = 0; e < 4; e++) acc[mi][nt][e] = 0.0f;
    mma_chunk(acc, aH, aL, bH, bL);
    epilogue<0, 0>(acc, bn, nullptr, OutN, m0, warp_m, warp_n, lane);

    __syncthreads();                 // frags consumed; safe to overwrite B
    stage_B(smem, Bsh, Bsl, tid);
    __syncthreads();

#pragma unroll
    for (int mi = 0; mi < 2; mi++)
#pragma unroll
        for (int nt = 0; nt < 8; nt++)
#pragma unroll
            for (int e = 0; e < 4; e++) acc[mi][nt][e] = 0.0f;
    mma_chunk(acc, aH, aL, bH, bL);
    epilogue<0, 0>(acc, bs, nullptr, OutS, m0, warp_m, warp_n, lane);
}

// ---------------------------------------------------------------------------
// Weight conversion: fp32 W[K,N] -> bf16 hi/lo B[N,K]
// ---------------------------------------------------------------------------
__global__ void wconv_kernel(const float* __restrict__ lw2,
                             const float* __restrict__ sw,
                             const float* __restrict__ nw,
                             const float* __restrict__ gw1,
                             const float* __restrict__ gw2) {
    int idx = blockIdx.x * blockDim.x + threadIdx.x;
    if (idx >= WSLOTS * 16384) return;
    int slot = idx >> 14;
    int within = idx & 16383;
    int n = within >> 7;
    int k = within & 127;
    const float* src;
    if (slot == 0) {
        src = lw2 + k * 128 + n;
    } else {
        int l = (slot - 1) / 5, j = (slot - 1) % 5;
        if (j == 0)      src = nw  + (size_t)l * 16384 + k * 128 + n;
        else if (j == 1) src = sw  + (size_t)l * 16384 + k * 128 + n;
        else if (j == 2) src = gw1 + (size_t)l * 32768 + k * 128 + n;
        else if (j == 3) src = gw1 + (size_t)l * 32768 + 16384 + k * 128 + n;
        else             src = gw2 + (size_t)l * 16384 + k * 128 + n;
    }
    float v = *src;
    __nv_bfloat16 hi = __float2bfloat16(v);
    __nv_bfloat16 lo = __float2bfloat16(v - __bfloat162float(hi));
    g_wbh[idx] = hi;
    g_wbl[idx] = lo;
}

// ---------------------------------------------------------------------------
// CSR build: count -> scan -> fill
// ---------------------------------------------------------------------------
__global__ void k_zero_cnt() {
    int i = blockIdx.x * blockDim.x + threadIdx.x;
    if (i < NN) g_cnt[i] = 0;
}
__global__ void k_count(const int* __restrict__ ei) {
    int e = blockIdx.x * blockDim.x + threadIdx.x;
    if (e < EE) atomicAdd(&g_cnt[ei[e]], 1);
}
__global__ void k_blocksum() {
    __shared__ int sh[256];
    int i = blockIdx.x * 256 + threadIdx.x;
    int v = (i < NN) ? g_cnt[i] : 0;
    sh[threadIdx.x] = v;
    __syncthreads();
    for (int s = 128; s; s >>= 1) {
        if (threadIdx.x < s) sh[threadIdx.x] += sh[threadIdx.x + s];
        __syncthreads();
    }
    if (threadIdx.x == 0) g_bsum[blockIdx.x] = sh[0];
}
__global__ void k_scan_bsum() {
    __shared__ int sh[512];
    int t = threadIdx.x;
    sh[t] = (t < SCAN_BLOCKS) ? g_bsum[t] : 0;
    __syncthreads();
    for (int off = 1; off < 512; off <<= 1) {
        int v = (t >= off) ? sh[t - off] : 0;
        __syncthreads();
        sh[t] += v;
        __syncthreads();
    }
    if (t < SCAN_BLOCKS) g_boff[t] = sh[t] - g_bsum[t];
}
__global__ void k_rowstart() {
    __shared__ int sh[256];
    int i = blockIdx.x * 256 + threadIdx.x;
    int v = (i < NN) ? g_cnt[i] : 0;
    sh[threadIdx.x] = v;
    __syncthreads();
    for (int off = 1; off < 256; off <<= 1) {
        int u = (threadIdx.x >= off) ? sh[threadIdx.x - off] : 0;
        __syncthreads();
        sh[threadIdx.x] += u;
        __syncthreads();
    }
    if (i < NN) {
        int excl = sh[threadIdx.x] - v + g_boff[blockIdx.x];
        g_rowstart[i] = excl;
        g_cursor[i] = excl;
        if (i == NN - 1) g_rowstart[NN] = excl + v;
    }
}
__global__ void k_fill(const int* __restrict__ ei, const float* __restrict__ ev) {
    int e = blockIdx.x * blockDim.x + threadIdx.x;
    if (e >= EE) return;
    int row = ei[e];
    int pos = atomicAdd(&g_cursor[row], 1);
    g_ecol[pos] = ei[EE + e];
    g_eval[pos] = ev[e];
}

// ---------------------------------------------------------------------------
// Pull aggregation: one warp per row (no atomics).
// ---------------------------------------------------------------------------
__global__ void k_aggr() {
    int r = blockIdx.x * 8 + (threadIdx.x >> 5);
    if (r >= NN) return;
    int lane = threadIdx.x & 31;
    int s = g_rowstart[r];
    int e = g_rowstart[r + 1];
    float acc0 = 0.f, acc1 = 0.f, acc2 = 0.f, acc3 = 0.f;
    for (int j = s; j < e; j++) {
        int c = __ldg(&g_ecol[j]);
        float v = __ldg(&g_eval[j]);
        const float* srow = g_nb + (size_t)c * CC + lane;
        acc0 = fmaf(__ldg(srow),      v, acc0);
        acc1 = fmaf(__ldg(srow + 32), v, acc1);
        acc2 = fmaf(__ldg(srow + 64), v, acc2);
        acc3 = fmaf(__ldg(srow + 96), v, acc3);
    }
    float* d = g_aggr + (size_t)r * CC + lane;
    d[0]  = acc0;
    d[32] = acc1;
    d[64] = acc2;
    d[96] = acc3;
}

// ---------------------------------------------------------------------------
// Lift stage 1 + LayerNorm
// ---------------------------------------------------------------------------
__global__ void lift_hidden_kernel(const float* __restrict__ x,
                                   const float* __restrict__ w1,
                                   const float* __restrict__ b1) {
    int idx = blockIdx.x * blockDim.x + threadIdx.x;
    if (idx >= NN * CC) return;
    int n = idx >> 7;
    int c = idx & 127;
    const float* xr = x + (size_t)n * 9 + 3;
    float acc = b1[c];
#pragma unroll
    for (int i = 0; i < 6; i++)
        acc = fmaf(xr[i], w1[i * CC + c], acc);
    g_u[idx] = gelu_f(acc);
}

__global__ void ln_kernel(const float* __restrict__ h,
                          const float* __restrict__ g,
                          const float* __restrict__ b,
                          float* __restrict__ out) {
    int n = blockIdx.x * 8 + (threadIdx.x >> 5);
    if (n >= NN) return;
    int lane = threadIdx.x & 31;
    const float* r = h + (size_t)n * CC;
    float v[4];
    float s = 0.f;
#pragma unroll
    for (int i = 0; i < 4; i++) { v[i] = r[lane + i * 32]; s += v[i]; }
#pragma unroll
    for (int o = 16; o; o >>= 1) s += __shfl_xor_sync(0xffffffffu, s, o);
    float mu = s * (1.f / 128.f);
    float q = 0.f;
#pragma unroll
    for (int i = 0; i < 4; i++) { float d = v[i] - mu; q = fmaf(d, d, q); }
#pragma unroll
    for (int o = 16; o; o >>= 1) q += __shfl_xor_sync(0xffffffffu, q, o);
    float inv = rsqrtf(q * (1.f / 128.f) + 1e-5f);
#pragma unroll
    for (int i = 0; i < 4; i++) {
        int c = lane + i * 32;
        out[(size_t)n * CC + c] = fmaf((v[i] - mu) * inv, g[c], b[c]);
    }
}

// ---------------------------------------------------------------------------
extern "C" void kernel_launch(void* const* d_in, const int* in_sizes, int n_in,
                              void* d_out, int out_size) {
    const float* x   = (const float*)d_in[0];
    const int*   ei  = (const int*)d_in[1];
    const float* ev  = (const float*)d_in[2];
    const float* lw1 = (const float*)d_in[3];
    const float* lb1 = (const float*)d_in[4];
    const float* lw2 = (const float*)d_in[5];
    const float* lb2 = (const float*)d_in[6];
    const float* sw  = (const float*)d_in[7];
    const float* sb  = (const float*)d_in[8];
    const float* nw  = (const float*)d_in[9];
    const float* nbw = (const float*)d_in[10];
    const float* gw1 = (const float*)d_in[11];
    const float* gb1 = (const float*)d_in[12];
    const float* gw2 = (const float*)d_in[13];
    const float* gb2 = (const float*)d_in[14];
    const float* ng  = (const float*)d_in[15];
    const float* nbt = (const float*)d_in[16];
    float* out = (float*)d_out;

    float *h, *nbuf, *selfb, *aggr, *u;
    cudaGetSymbolAddress((void**)&h, g_h);
    cudaGetSymbolAddress((void**)&nbuf, g_nb);
    cudaGetSymbolAddress((void**)&selfb, g_self);
    cudaGetSymbolAddress((void**)&aggr, g_aggr);
    cudaGetSymbolAddress((void**)&u, g_u);
    __nv_bfloat16 *wbh, *wbl;
    cudaGetSymbolAddress((void**)&wbh, g_wbh);
    cudaGetSymbolAddress((void**)&wbl, g_wbl);

    cudaFuncSetAttribute(gemm_mma<0, 0>, cudaFuncAttributeMaxDynamicSharedMemorySize, SM_TOTAL);
    cudaFuncSetAttribute(gemm_mma<1, 0>, cudaFuncAttributeMaxDynamicSharedMemorySize, SM_TOTAL);
    cudaFuncSetAttribute(gemm_mma<0, 1>, cudaFuncAttributeMaxDynamicSharedMemorySize, SM_TOTAL);
    cudaFuncSetAttribute(gemm_ns, cudaFuncAttributeMaxDynamicSharedMemorySize, SM_TOTAL);

    const int GB = (NN + 127) / 128;

    // Pre-split weights + CSR build (once per launch)
    wconv_kernel<<<(WSLOTS * 16384 + 255) / 256, 256>>>(lw2, sw, nw, gw1, gw2);
    k_zero_cnt<<<SCAN_BLOCKS, 256>>>();
    k_count<<<(EE + 255) / 256, 256>>>(ei);
    k_blocksum<<<SCAN_BLOCKS, 256>>>();
    k_scan_bsum<<<1, 512>>>();
    k_rowstart<<<SCAN_BLOCKS, 256>>>();
    k_fill<<<(EE + 255) / 256, 256>>>(ei, ev);

    // Lift
    lift_hidden_kernel<<<(NN * CC + 255) / 256, 256>>>(x, lw1, lb1);
    gemm_mma<0, 0><<<GB, 256, SM_TOTAL>>>(u, nullptr, wbh, wbl, lb2, nullptr, h, 1);

    for (int l = 0; l < 2; l++) {
        const __nv_bfloat16* nh = wbh + (size_t)(1 + 5 * l) * 16384;
        const __nv_bfloat16* nl = wbl + (size_t)(1 + 5 * l) * 16384;
        const __nv_bfloat16* sh = wbh + (size_t)(2 + 5 * l) * 16384;
        const __nv_bfloat16* sl = wbl + (size_t)(2 + 5 * l) * 16384;
        const __nv_bfloat16* g1h = wbh + (size_t)(3 + 5 * l) * 16384;
        const __nv_bfloat16* g1l = wbl + (size_t)(3 + 5 * l) * 16384;
        const __nv_bfloat16* g2h = wbh + (size_t)(5 + 5 * l) * 16384;
        const __nv_bfloat16* g2l = wbl + (size_t)(5 + 5 * l) * 16384;

        // neighbor + self (fused: stage h once)
        gemm_ns<<<GB, 256, SM_TOTAL>>>(h, nh, nl, nbw + l * CC, nbuf,
                                       sh, sl, sb + l * CC, selfb);
        // aggr[row] = sum ev * neighbor[col]  (pull, no atomics)
        k_aggr<<<(NN + 7) / 8, 256>>>();
        // u = gelu([self_f, aggr] @ Wg1 + bg1)
        gemm_mma<1, 0><<<GB, 256, SM_TOTAL>>>(selfb, aggr, g1h, g1l, gb1 + l * CC, nullptr, u, 2);
        // h = h + u @ Wg2 + bg2
        gemm_mma<0, 1><<<GB, 256, SM_TOTAL>>>(u, nullptr, g2h, g2l, gb2 + l * CC, h, h, 1);
    }

    ln_kernel<<<(NN + 7) / 8, 256>>>(h, ng, nbt, out);
}